// round 6
// baseline (speedup 1.0000x reference)
#include <cuda_runtime.h>
#include <cuda_bf16.h>
#include <cstdint>
#include <cstddef>

// ---------------- problem constants ----------------
#define B_SZ   256
#define T_SZ   1024
#define I_SZ   128
#define H_SZ   256
#define CLC    8                 // CTAs per cluster (hidden split)
#define NB     16                // batch rows per cluster
#define GRID_CTAS 128
#define THREADS2 512             // recurrent kernel: 16 warps

// ---------------- recurrent kernel SMEM ----------------
// A: [128 rows][SA2] bf16, cols 0..255 hi, 256..511 lo (short-weights only)
// B: [16 rows][SB2] bf16, cols 0..255 hi, 256..511 lo
// scr: [2][128][20] fp32 K-split partials
#define SA2 520                              // els; 1040B = 65*16B odd -> conflict-free ldmatrix
#define SB2 520
#define A_BYTES2 (128 * SA2 * 2)             // 133120
#define B_OFF2   A_BYTES2
#define B_BYTES2 (NB * SB2 * 2)              // 16640
#define SCR_OFF2 (B_OFF2 + B_BYTES2)         // 149760
#define SCR_S    20
#define SMEM2    (SCR_OFF2 + 2 * 128 * SCR_S * 4)  // 170240

// ---------------- precompute kernel SMEM ----------------
#define SA3 264                              // 528B = 33*16B odd
#define PC_A_BYTES (128 * SA3 * 2)           // 67584
#define SMEM3 (2 * PC_A_BYTES)               // 135168

// x-projection scratch: xp[t*B + b][g*256 + h], fp32, 1 GiB
__device__ float g_xproj[268435456];
// packed (hi | lo<<16) bf16 short-state exchange, ping-pong, in L2
__device__ uint32_t g_short_pack[2][B_SZ * H_SZ];

// ---------------- helpers ----------------
__device__ __forceinline__ uint32_t smem_u32(const void* p) {
    uint32_t a;
    asm("{ .reg .u64 t; cvta.to.shared.u64 t, %1; cvt.u32.u64 %0, t; }" : "=r"(a) : "l"(p));
    return a;
}
__device__ __forceinline__ void cluster_sync() {
    asm volatile("barrier.cluster.arrive.aligned;" ::: "memory");
    asm volatile("barrier.cluster.wait.aligned;"   ::: "memory");
}
__device__ __forceinline__ void ldsm4(uint32_t* r, uint32_t addr) {
    asm volatile("ldmatrix.sync.aligned.m8n8.x4.shared.b16 {%0,%1,%2,%3}, [%4];"
                 : "=r"(r[0]), "=r"(r[1]), "=r"(r[2]), "=r"(r[3]) : "r"(addr));
}
__device__ __forceinline__ void mma16816(float* d, const uint32_t* a, const uint32_t* b) {
    asm volatile("mma.sync.aligned.m16n8k16.row.col.f32.bf16.bf16.f32 "
                 "{%0,%1,%2,%3}, {%4,%5,%6,%7}, {%8,%9}, {%0,%1,%2,%3};"
                 : "+f"(d[0]), "+f"(d[1]), "+f"(d[2]), "+f"(d[3])
                 : "r"(a[0]), "r"(a[1]), "r"(a[2]), "r"(a[3]), "r"(b[0]), "r"(b[1]));
}
__device__ __forceinline__ float sigm(float x) { return 1.0f / (1.0f + __expf(-x)); }
__device__ __forceinline__ float tanh_(float x) {
    float e = __expf(-2.0f * fabsf(x));
    return copysignf((1.0f - e) / (1.0f + e), x);
}
__device__ __forceinline__ void split_bf16(float v, __nv_bfloat16& hi, __nv_bfloat16& lo) {
    hi = __float2bfloat16_rn(v);
    lo = __float2bfloat16_rn(v - __bfloat162float(hi));
}

// ================= precompute kernel: xp = x @ Wx (all gates, all t) =================
__global__ void __launch_bounds__(256, 1)
xproj_kernel(const float* __restrict__ x,
             const float* __restrict__ Wf_x, const float* __restrict__ Wip_x,
             const float* __restrict__ Wit_x, const float* __restrict__ Wo_x)
{
    extern __shared__ char smem[];
    __nv_bfloat16* Ax = (__nv_bfloat16*)smem;                  // [128][264] hi|lo
    __nv_bfloat16* Bw = (__nv_bfloat16*)(smem + PC_A_BYTES);   // [128][264] hi|lo

    const int tid = threadIdx.x;
    const int w   = tid >> 5;
    const int l   = tid & 31;
    const int t   = blockIdx.x >> 1;
    const int bh  = (blockIdx.x & 1) * 128;          // batch half
    const int g   = blockIdx.y >> 1;
    const int hb  = (blockIdx.y & 1) * 128;          // hidden half
    const float* Wxg = (g == 0) ? Wf_x : (g == 1) ? Wip_x : (g == 2) ? Wit_x : Wo_x;

    // stage A = x block [128 b][128 i], split hi/lo
    {
        const int r    = tid >> 1;
        const int half = (tid & 1) * 64;
        const float* xr = x + ((size_t)(bh + r) * T_SZ + t) * I_SZ + half;
        #pragma unroll 4
        for (int q = 0; q < 64; q++) {
            __nv_bfloat16 hi, lo;
            split_bf16(xr[q], hi, lo);
            Ax[r * SA3 + half + q]       = hi;
            Ax[r * SA3 + 128 + half + q] = lo;
        }
    }
    // stage B = Wt [128 n(h)][128 k(i)], split hi/lo
    {
        const int kk = tid >> 1;
        const int nh = (tid & 1) * 64;
        const float* wr = Wxg + (size_t)kk * H_SZ + hb + nh;
        #pragma unroll 4
        for (int n = 0; n < 64; n++) {
            __nv_bfloat16 hi, lo;
            split_bf16(wr[n], hi, lo);
            Bw[(nh + n) * SA3 + kk]       = hi;
            Bw[(nh + n) * SA3 + 128 + kk] = lo;
        }
    }
    __syncthreads();

    const uint32_t a_lane = smem_u32(Ax) +
        (uint32_t)(((16 * w + (l & 7) + 8 * ((l >> 3) & 1)) * SA3 + 8 * (l >> 4)) * 2);
    const uint32_t b_lane = smem_u32(Bw) +
        (uint32_t)((((l & 7) + 8 * (l >> 4)) * SA3 + 8 * ((l >> 3) & 1)) * 2);

    float acc[16][4];
    #pragma unroll
    for (int i = 0; i < 16; i++)
        #pragma unroll
        for (int j = 0; j < 4; j++) acc[i][j] = 0.0f;

    #pragma unroll 2
    for (int kc = 0; kc < 8; kc++) {
        uint32_t ah[4], al[4];
        ldsm4(ah, a_lane + kc * 32);
        ldsm4(al, a_lane + 256 + kc * 32);          // lo at +128 els
        #pragma unroll
        for (int nt = 0; nt < 8; nt++) {
            uint32_t bh4[4], bl4[4];
            uint32_t ba = b_lane + (uint32_t)(nt * 16 * SA3 * 2) + kc * 32;
            ldsm4(bh4, ba);
            ldsm4(bl4, ba + 256);
            mma16816(acc[2 * nt],     ah, bh4 + 0);
            mma16816(acc[2 * nt + 1], ah, bh4 + 2);
            mma16816(acc[2 * nt],     al, bh4 + 0);
            mma16816(acc[2 * nt + 1], al, bh4 + 2);
            mma16816(acc[2 * nt],     ah, bl4 + 0);
            mma16816(acc[2 * nt + 1], ah, bl4 + 2);
        }
    }

    // store to xp
    {
        const size_t row0 = (size_t)t * B_SZ + bh + 16 * w + (l >> 2);
        const int    cb   = g * 256 + hb + (l & 3) * 2;
        #pragma unroll
        for (int nt = 0; nt < 8; nt++) {
            *(float2*)&g_xproj[row0 * 1024 + cb + nt * 16]           = make_float2(acc[2*nt][0], acc[2*nt][1]);
            *(float2*)&g_xproj[(row0 + 8) * 1024 + cb + nt * 16]     = make_float2(acc[2*nt][2], acc[2*nt][3]);
            *(float2*)&g_xproj[row0 * 1024 + cb + nt * 16 + 8]       = make_float2(acc[2*nt+1][0], acc[2*nt+1][1]);
            *(float2*)&g_xproj[(row0 + 8) * 1024 + cb + nt * 16 + 8] = make_float2(acc[2*nt+1][2], acc[2*nt+1][3]);
        }
    }
}

// ================= recurrent kernel =================
__global__ void __launch_bounds__(THREADS2, 1) __cluster_dims__(CLC, 1, 1)
lstm_rec_kernel(const float* __restrict__ Wf_h,  const float* __restrict__ bf,
                const float* __restrict__ Wip_h, const float* __restrict__ bip,
                const float* __restrict__ Wit_h, const float* __restrict__ bit_,
                const float* __restrict__ Wo_h,  const float* __restrict__ bo,
                float* __restrict__ out)
{
    extern __shared__ char smem[];
    __nv_bfloat16* As = (__nv_bfloat16*)smem;
    __nv_bfloat16* Bs = (__nv_bfloat16*)(smem + B_OFF2);
    float*         scr = (float*)(smem + SCR_OFF2);   // [2][128][20]

    const int tid = threadIdx.x;
    const int w   = tid >> 5;
    const int l   = tid & 31;
    const int m   = w & 7;                  // M-tile (16 gate rows)
    const int ks  = w >> 3;                 // K half (chunks ks*8 .. ks*8+7)
    const int c   = blockIdx.x & (CLC - 1);
    const int grp = blockIdx.x >> 3;
    const int b0  = grp * NB;

    // ---- stage A (short-part weights, K=256) hi|lo into SMEM ----
    {
        const int r  = tid >> 2;            // 0..127 : row = 4*h_local + gate
        const int kq = (tid & 3) * 64;
        const int g  = r & 3;
        const int hs = 32 * c + (r >> 2);
        const float* Wh = (g == 0) ? Wf_h : (g == 1) ? Wip_h : (g == 2) ? Wit_h : Wo_h;
        #pragma unroll 4
        for (int k = kq; k < kq + 64; k++) {
            __nv_bfloat16 hi, lo;
            split_bf16(Wh[(size_t)k * H_SZ + hs], hi, lo);
            As[r * SA2 + k]       = hi;
            As[r * SA2 + 256 + k] = lo;
        }
    }
    __syncthreads();

    // ---- load A fragments into registers (once) ----
    uint32_t ah[8][4], al[8][4];
    {
        const uint32_t a_lane = smem_u32(As) +
            (uint32_t)(((16 * m + (l & 7) + 8 * ((l >> 3) & 1)) * SA2 + 8 * (l >> 4)) * 2);
        #pragma unroll
        for (int kc = 0; kc < 8; kc++) {
            ldsm4(ah[kc], a_lane + (ks * 8 + kc) * 32);
            ldsm4(al[kc], a_lane + 512 + (ks * 8 + kc) * 32);   // lo at +256 els
        }
    }

    const uint32_t b_lane = smem_u32(Bs) +
        (uint32_t)((((l & 7) + 8 * (l >> 4)) * SB2 + 8 * ((l >> 3) & 1)) * 2);

    // ---- epilogue mapping: 1 cell per thread: hl = tid>>4 (0..31), bb = tid&15 ----
    const int hl = tid >> 4;
    const int bb = tid & 15;
    const int hg = 32 * c + hl;
    const float biasv[4] = {bf[hg], bip[hg], bit_[hg], bo[hg]};
    float longv = 0.0f;

    // ---- zero step-0 short buffer (own slice) ----
    g_short_pack[0][(b0 + (tid >> 5)) * H_SZ + 32 * c + (tid & 31)] = 0u;

    __syncthreads();
    cluster_sync();

    #pragma unroll 1
    for (int t = 0; t < T_SZ; t++) {
        const int cur = t & 1;
        const int nxt = cur ^ 1;

        // ===== stage B tile (short only): row i = tid>>5, 8 h-cols =====
        {
            const int i   = tid >> 5;
            const int hb8 = (tid & 31) * 8;
            const uint32_t* srow = g_short_pack[cur] + (size_t)(b0 + i) * H_SZ + hb8;
            uint4 v0 = __ldcg((const uint4*)srow);
            uint4 v1 = __ldcg((const uint4*)(srow + 4));
            __nv_bfloat16* brow = Bs + i * SB2;
            *(uint32_t*)&brow[hb8]           = __byte_perm(v0.x, v0.y, 0x5410);
            *(uint32_t*)&brow[hb8 + 2]       = __byte_perm(v0.z, v0.w, 0x5410);
            *(uint32_t*)&brow[hb8 + 4]       = __byte_perm(v1.x, v1.y, 0x5410);
            *(uint32_t*)&brow[hb8 + 6]       = __byte_perm(v1.z, v1.w, 0x5410);
            *(uint32_t*)&brow[256 + hb8]     = __byte_perm(v0.x, v0.y, 0x7632);
            *(uint32_t*)&brow[256 + hb8 + 2] = __byte_perm(v0.z, v0.w, 0x7632);
            *(uint32_t*)&brow[256 + hb8 + 4] = __byte_perm(v1.x, v1.y, 0x7632);
            *(uint32_t*)&brow[256 + hb8 + 6] = __byte_perm(v1.z, v1.w, 0x7632);
        }

        // ===== prefetch x-projection for this step (consumed in epilogue) =====
        float xpv[4];
        {
            const float* xr = g_xproj + ((size_t)t * B_SZ + b0 + bb) * 1024 + hg;
            #pragma unroll
            for (int g = 0; g < 4; g++) xpv[g] = __ldcg(xr + g * 256);
        }
        __syncthreads();

        // ===== GEMM: 3-term bf16 split, A frags in registers =====
        float acc0[4] = {0.f, 0.f, 0.f, 0.f};
        float acc1[4] = {0.f, 0.f, 0.f, 0.f};
        #pragma unroll
        for (int kc = 0; kc < 8; kc++) {
            uint32_t bh4[4], bl4[4];
            const uint32_t kb = (uint32_t)(ks * 8 + kc) * 32;
            ldsm4(bh4, b_lane + kb);
            ldsm4(bl4, b_lane + 512 + kb);
            mma16816(acc0, ah[kc], bh4 + 0);
            mma16816(acc1, ah[kc], bh4 + 2);
            mma16816(acc0, al[kc], bh4 + 0);
            mma16816(acc1, al[kc], bh4 + 2);
            mma16816(acc0, ah[kc], bl4 + 0);
            mma16816(acc1, ah[kc], bl4 + 2);
        }

        // ===== store K-split partials to scratch =====
        {
            float* s = scr + ks * (128 * SCR_S);
            const int r0 = 16 * m + (l >> 2);
            const int c0 = (l & 3) * 2;
            *(float2*)&s[r0 * SCR_S + c0]           = make_float2(acc0[0], acc0[1]);
            *(float2*)&s[(r0 + 8) * SCR_S + c0]     = make_float2(acc0[2], acc0[3]);
            *(float2*)&s[r0 * SCR_S + c0 + 8]       = make_float2(acc1[0], acc1[1]);
            *(float2*)&s[(r0 + 8) * SCR_S + c0 + 8] = make_float2(acc1[2], acc1[3]);
        }
        __syncthreads();

        // ===== epilogue: 1 cell (hl, bb) =====
        {
            float z[4];
            #pragma unroll
            for (int g = 0; g < 4; g++) {
                const int r = 4 * hl + g;
                z[g] = scr[r * SCR_S + bb] + scr[128 * SCR_S + r * SCR_S + bb]
                     + xpv[g] + biasv[g];
            }
            float f  = sigm(z[0]);
            float ip = sigm(z[1]);
            float pt = tanh_(z[2]);
            longv = f * longv + ip * pt;
            float o  = sigm(z[3]);
            float ns = tanh_(longv) * o;
            __nv_bfloat16 hi, lo;
            split_bf16(ns, hi, lo);
            uint32_t pk = (uint32_t)__bfloat16_as_ushort(hi) |
                          ((uint32_t)__bfloat16_as_ushort(lo) << 16);
            const int bbg = b0 + bb;
            __stcg(&g_short_pack[nxt][(size_t)bbg * H_SZ + hg], pk);
            if (t == T_SZ - 1) {
                out[(size_t)bbg * H_SZ + hg]                        = ns;
                out[(size_t)B_SZ * H_SZ + (size_t)bbg * H_SZ + hg]  = longv;
            }
        }

        cluster_sync();  // publish short state; guards Bs/scr reuse
    }
}

// ---------------- launch ----------------
extern "C" void kernel_launch(void* const* d_in, const int* in_sizes, int n_in,
                              void* d_out, int out_size)
{
    (void)in_sizes; (void)n_in; (void)out_size;
    const float* x     = (const float*)d_in[0];
    const float* Wf_h  = (const float*)d_in[1];
    const float* Wf_x  = (const float*)d_in[2];
    const float* bf    = (const float*)d_in[3];
    const float* Wip_h = (const float*)d_in[4];
    const float* Wip_x = (const float*)d_in[5];
    const float* bip   = (const float*)d_in[6];
    const float* Wit_h = (const float*)d_in[7];
    const float* Wit_x = (const float*)d_in[8];
    const float* bit_  = (const float*)d_in[9];
    const float* Wo_h  = (const float*)d_in[10];
    const float* Wo_x  = (const float*)d_in[11];
    const float* bo    = (const float*)d_in[12];
    float* out = (float*)d_out;

    cudaFuncSetAttribute(xproj_kernel,
                         cudaFuncAttributeMaxDynamicSharedMemorySize, SMEM3);
    cudaFuncSetAttribute(lstm_rec_kernel,
                         cudaFuncAttributeMaxDynamicSharedMemorySize, SMEM2);

    dim3 pgrid(2048, 8);
    xproj_kernel<<<pgrid, 256, SMEM3>>>(x, Wf_x, Wip_x, Wit_x, Wo_x);

    lstm_rec_kernel<<<GRID_CTAS, THREADS2, SMEM2>>>(
        Wf_h, bf, Wip_h, bip, Wit_h, bit_, Wo_h, bo, out);
}